// round 10
// baseline (speedup 1.0000x reference)
#include <cuda_runtime.h>
#include <cstdint>

#define BB   4
#define TT   1024
#define CHN  4
#define FF   481
#define KK   48
#define PPV  16
#define FT   37          // freq tile (13 * 37 = 481 exactly)
#define NTILE 13
#define FRB  4           // frames per block
#define NTHREADS 256     // 4 frames * 64 gemm threads

// ---------- packed f32x2 helpers ----------
__device__ __forceinline__ unsigned long long fma2(unsigned long long a,
                                                   unsigned long long b,
                                                   unsigned long long c) {
    unsigned long long d;
    asm("fma.rn.f32x2 %0, %1, %2, %3;" : "=l"(d) : "l"(a), "l"(b), "l"(c));
    return d;
}
__device__ __forceinline__ float2 u2f(unsigned long long v) {
    unsigned int lo, hi;
    asm("mov.b64 {%0, %1}, %2;" : "=r"(lo), "=r"(hi) : "l"(v));
    return make_float2(__uint_as_float(lo), __uint_as_float(hi));
}
__device__ __forceinline__ unsigned long long pkpair(float lo, float hi) {
    unsigned long long r;
    asm("mov.b64 %0, {%1, %2};" : "=l"(r)
        : "r"(__float_as_uint(lo)), "r"(__float_as_uint(hi)));
    return r;
}

// smem layout (floats):
//   sband1 : [FT][64]   per-kg slot kg*4: (br,bi) of k=kg and k=kg+16    2368
//   sband2 : [FT][32]   per-kg slot kg*2: (br,bi) of k=kg+32             1184
//   scov   : [FRB][41][17]  hermitian-compressed (odd stride: no conflicts) 2788
//   sadj   : [FRB][FT][36]  duplicated scalars, 144B rows (16B aligned)  5328
// union 11668 floats = 46,672 B (+2 KB sC = 48,720 <= 48 KB static).
// Epilogue bc buffer overlays: [FRB*KK][17] float2 = 6528 floats.
#define COVS 17
#define ADJS 36
#define BCS  17
#define SB1_OFF  0
#define SB2_OFF  (FT*64)
#define SCOV_OFF (FT*96)
#define SADJ_OFF (SCOV_OFF + FRB*41*COVS)
#define SU_FLOATS (SADJ_OFF + FRB*FT*ADJS)

__global__ void __launch_bounds__(NTHREADS, 4)
frame_kernel(const float* __restrict__ binr, const float* __restrict__ bini,
             const float* __restrict__ bandr, const float* __restrict__ bandi,
             const float* __restrict__ c2r,  const float* __restrict__ c2i,
             float* __restrict__ out)
{
    __shared__ __align__(16) float su[SU_FLOATS];
    __shared__ float sC[512];           // [0..255]=Cr[p][c], [256..511]=Ci[p][c]

    const int tid = threadIdx.x;
    const int g0  = blockIdx.x * FRB;   // first global frame of this block

    for (int i = tid; i < 512; i += NTHREADS)
        sC[i] = (i < 256) ? c2r[i] : c2i[i - 256];

    // GEMM coords: 64 threads per frame = 16 kgroups x 4 cu quarters.
    const int fr_g = tid >> 6;
    const int tf   = tid & 63;
    const int kg   = tf & 15;           // thread's k = kg + 16*m, m<3
    const int cu   = tf >> 4;           // cu0:(01)(02) cu1:(03)(12) cu2:(13)(23) cu3:diag

    unsigned long long acc[4][3];
#pragma unroll
    for (int j = 0; j < 4; j++)
#pragma unroll
        for (int m = 0; m < 3; m++) acc[j][m] = 0ull;

    float* sband1 = su + SB1_OFF;
    float* sband2 = su + SB2_OFF;
    float* scov   = su + SCOV_OFF;
    float* sadj   = su + SADJ_OFF;

    // ---- bin prefetch state (one bin per thread, 164 active threads) ----
    const bool pf_on = tid < FRB * 41;
    const int  pf_fr = tid / 41;
    const int  pf_fe = tid - pf_fr * 41;
    const float* pf_xr = binr + (size_t)(g0 + pf_fr) * CHN * FF;
    const float* pf_xi = bini + (size_t)(g0 + pf_fr) * CHN * FF;
    float pr[4], pq[4];

    // prefetch tile 0
    if (pf_on) {
        int f = -2 + pf_fe;
        f = f < 0 ? 0 : (f > FF - 1 ? FF - 1 : f);
#pragma unroll
        for (int c = 0; c < 4; c++) { pr[c] = pf_xr[c * FF + f]; pq[c] = pf_xi[c * FF + f]; }
    }

    for (int tile = 0; tile < NTILE; tile++) {
        const int ft0 = tile * FT;
        __syncthreads();   // previous GEMM done reading su before overwrite

        // ---- stage band tile into per-kg slots ----
        for (int i = tid; i < FT * KK; i += NTHREADS) {
            int ff = i / KK, k = i - ff * KK;
            int f = ft0 + ff;
            unsigned long long v = pkpair(bandr[f * KK + k], bandi[f * KK + k]);
            int kq = k & 15, m = k >> 4;
            if (m < 2)
                *reinterpret_cast<unsigned long long*>(sband1 + ff * 64 + kq * 4 + m * 2) = v;
            else
                *reinterpret_cast<unsigned long long*>(sband2 + ff * 32 + kq * 2) = v;
        }

        // ---- covariance from prefetched registers ----
        if (pf_on) {
            float pw = 0.f;
#pragma unroll
            for (int c = 0; c < 4; c++) pw += pr[c] * pr[c] + pq[c] * pq[c];
            float inv = 1.0f / fmaxf(pw, 1e-20f);
            float* dst = scov + (pf_fr * 41 + pf_fe) * COVS;
            int w = 0;
#pragma unroll
            for (int a = 0; a < 4; a++)
#pragma unroll
                for (int b = a + 1; b < 4; b++) {
                    dst[w++] = (pr[a] * pr[b] + pq[a] * pq[b]) * inv;
                    dst[w++] = (pq[a] * pr[b] - pr[a] * pq[b]) * inv;
                }
#pragma unroll
            for (int c = 0; c < 4; c++)
                dst[12 + c] = (pr[c] * pr[c] + pq[c] * pq[c]) * inv;
        }
        __syncthreads();

        // ---- phase-adjusted adj, DUPLICATED: [p,p,q,q]x6 + [d,d]x4 ----
        for (int i = tid; i < FRB * FT; i += NTHREADS) {
            int fr = i / FT, ff = i - fr * FT;
            int f = ft0 + ff;
            int fl = (f == 0) ? 0 : ((f == FF - 1) ? FF - 3 : f - 1);
            int fh = (f == 0) ? 2 : ((f == FF - 1) ? FF - 1 : f + 1);
            const float* c0 = scov + (fr * 41 + (ff + 2)) * COVS;
            const float* cl = scov + (fr * 41 + (fl - ft0 + 2)) * COVS;
            const float* ch = scov + (fr * 41 + (fh - ft0 + 2)) * COVS;
            float* dst = sadj + (fr * FT + ff) * ADJS;
#pragma unroll
            for (int t2 = 0; t2 < 6; t2++) {
                float r0 = c0[2 * t2], i0 = c0[2 * t2 + 1];
                float rl = cl[2 * t2], il = cl[2 * t2 + 1];
                float rh = ch[2 * t2], ih = ch[2 * t2 + 1];
                float zr = rl * rh + il * ih;          // conj(cov_l)*cov_h
                float zi = rl * ih - il * rh;
                float mag = sqrtf(r0 * r0 + i0 * i0);
                float zn = rsqrtf(fmaxf(zr * zr + zi * zi, 1e-38f));
                float p = mag * zr * zn;
                float q = mag * zi * zn;
                *reinterpret_cast<unsigned long long*>(dst + 4 * t2)     = pkpair(p, p);
                *reinterpret_cast<unsigned long long*>(dst + 4 * t2 + 2) = pkpair(q, q);
            }
#pragma unroll
            for (int c = 0; c < 4; c++) {
                float d = c0[12 + c];
                *reinterpret_cast<unsigned long long*>(dst + 24 + 2 * c) = pkpair(d, d);
            }
        }

        // ---- issue bin prefetch for next tile (latency hides under GEMM) ----
        if (pf_on && tile + 1 < NTILE) {
            int f = (tile + 1) * FT - 2 + pf_fe;
            f = f > FF - 1 ? FF - 1 : f;   // lower clamp impossible for tile>=1
#pragma unroll
            for (int c = 0; c < 4; c++) { pr[c] = pf_xr[c * FF + f]; pq[c] = pf_xi[c * FF + f]; }
        }
        __syncthreads();

        // ---- GEMM: 2x LDS.128 (v) + LDS.128 + LDS.64 (b) + 12 FMA2 ----
        const float* a_ptr = sadj + fr_g * FT * ADJS + cu * 8;
        const float* b1p   = sband1 + kg * 4;
        const float* b2p   = sband2 + kg * 2;
        for (int ff = 0; ff < FT; ff++) {
            float4 va = *reinterpret_cast<const float4*>(a_ptr);
            float4 vb = *reinterpret_cast<const float4*>(a_ptr + 4);
            float4 bq = *reinterpret_cast<const float4*>(b1p);
            float2 bz = *reinterpret_cast<const float2*>(b2p);
            unsigned long long v0 = pkpair(va.x, va.y), v1 = pkpair(va.z, va.w);
            unsigned long long v2 = pkpair(vb.x, vb.y), v3 = pkpair(vb.z, vb.w);
            unsigned long long b0 = pkpair(bq.x, bq.y), b1 = pkpair(bq.z, bq.w);
            unsigned long long b2 = pkpair(bz.x, bz.y);
            acc[0][0] = fma2(v0, b0, acc[0][0]);
            acc[0][1] = fma2(v0, b1, acc[0][1]);
            acc[0][2] = fma2(v0, b2, acc[0][2]);
            acc[1][0] = fma2(v1, b0, acc[1][0]);
            acc[1][1] = fma2(v1, b1, acc[1][1]);
            acc[1][2] = fma2(v1, b2, acc[1][2]);
            acc[2][0] = fma2(v2, b0, acc[2][0]);
            acc[2][1] = fma2(v2, b1, acc[2][1]);
            acc[2][2] = fma2(v2, b2, acc[2][2]);
            acc[3][0] = fma2(v3, b0, acc[3][0]);
            acc[3][1] = fma2(v3, b1, acc[3][1]);
            acc[3][2] = fma2(v3, b2, acc[3][2]);
            a_ptr += ADJS; b1p += 64; b2p += 32;
        }
    }

    // ---- epilogue: reconstruct bc, normalize, project ----
    __syncthreads();
    float2* bcb = reinterpret_cast<float2*>(su);   // [FRB*KK][BCS]

    {
        const int pi[6] = {0, 0, 0, 1, 1, 2};
        const int pj[6] = {1, 2, 3, 2, 3, 3};
#pragma unroll
        for (int m = 0; m < 3; m++) {
            int k = kg + 16 * m;
            float2* row = bcb + (fr_g * KK + k) * BCS;
            if (cu < 3) {
#pragma unroll
                for (int t2l = 0; t2l < 2; t2l++) {
                    int t2 = cu * 2 + t2l;
                    float2 s13 = u2f(acc[2 * t2l][m]);       // (Σp·br, Σp·bi)
                    float2 s42 = u2f(acc[2 * t2l + 1][m]);   // (Σq·br, Σq·bi)
                    row[pi[t2] * 4 + pj[t2]] = make_float2(s13.x - s42.y, s13.y + s42.x);
                    row[pj[t2] * 4 + pi[t2]] = make_float2(s13.x + s42.y, s13.y - s42.x);
                }
            } else {
#pragma unroll
                for (int d = 0; d < 4; d++)
                    row[d * 5] = u2f(acc[d][m]);             // (Σd·br, Σd·bi)
            }
        }
    }
    __syncthreads();

    for (int s = tid; s < FRB * KK; s += NTHREADS) {
        int fr = s / KK, k = s - fr * KK;
        const float2* row = bcb + (fr * KK + k) * BCS;
        float re[16], im[16];
#pragma unroll
        for (int c = 0; c < 16; c++) { float2 v = row[c]; re[c] = v.x; im[c] = v.y; }
        float ds = re[0] + re[5] + re[10] + re[15];
        float inv = 1.0f / fmaxf(ds, 1e-20f);
        int g = g0 + fr;
        int b = g >> 10, t = g & 1023;
        float* op = out + (((size_t)(b * KK + k)) * TT + t) * PPV;
#pragma unroll
        for (int p = 0; p < 16; p++) {
            float a = 0.f;
#pragma unroll
            for (int c = 0; c < 16; c++)
                a += sC[p * 16 + c] * re[c] - sC[256 + p * 16 + c] * im[c];
            op[p] = a * inv;
        }
    }
}

// ---- IIR over frames as a chunked parallel scan ----
#define IIR_L 32
__global__ void __launch_bounds__(512)
iir_kernel(float* __restrict__ out, const float* __restrict__ tau)
{
    __shared__ float zend[IIR_L * PPV];
    __shared__ float carry[IIR_L * PPV];
    const int bk  = blockIdx.x;          // b*KK + k
    const int k   = bk % KK;
    const int tid = threadIdx.x;
    const int p   = tid & 15;
    const int c   = tid >> 4;            // chunk 0..31

    float a = expf(-10.0f / tau[k]);
    float bcoef = 1.0f - a;
    float a2 = a * a, a4 = a2 * a2, a8 = a4 * a4, a16 = a8 * a8, pw = a16 * a16;

    float* base = out + (size_t)bk * (TT * PPV) + (size_t)c * (IIR_L * PPV) + p;

    float x[IIR_L];
#pragma unroll
    for (int i = 0; i < IIR_L; i++) x[i] = base[i * PPV];

    float y = (c == 0) ? x[0] : bcoef * x[0];
#pragma unroll
    for (int i = 1; i < IIR_L; i++) y = fmaf(a, y, bcoef * x[i]);
    zend[tid] = y;
    __syncthreads();

    if (tid < PPV) {
        float Y = zend[tid];             // chunk 0 end (exact)
        carry[tid] = 0.f;
#pragma unroll 4
        for (int cc = 1; cc < IIR_L; cc++) {
            carry[cc * PPV + tid] = Y;
            Y = fmaf(pw, Y, zend[cc * PPV + tid]);
        }
    }
    __syncthreads();

    float C = carry[tid];
    if (c == 0) {
        y = x[0];
        base[0] = y;
#pragma unroll
        for (int i = 1; i < IIR_L; i++) {
            y = fmaf(a, y, bcoef * x[i]);
            base[i * PPV] = y;
        }
    } else {
        y = C;
#pragma unroll
        for (int i = 0; i < IIR_L; i++) {
            y = fmaf(a, y, bcoef * x[i]);
            base[i * PPV] = y;
        }
    }
}

extern "C" void kernel_launch(void* const* d_in, const int* in_sizes, int n_in,
                              void* d_out, int out_size)
{
    const float* binr  = (const float*)d_in[0];
    const float* bini  = (const float*)d_in[1];
    const float* bandr = (const float*)d_in[2];
    const float* bandi = (const float*)d_in[3];
    const float* c2r   = (const float*)d_in[4];
    const float* c2i   = (const float*)d_in[5];
    const float* tau   = (const float*)d_in[6];
    float* out = (float*)d_out;

    frame_kernel<<<(BB * TT) / FRB, NTHREADS>>>(binr, bini, bandr, bandi, c2r, c2i, out);
    iir_kernel<<<BB * KK, 512>>>(out, tau);
}